// round 14
// baseline (speedup 1.0000x reference)
#include <cuda_runtime.h>
#include <cuda_fp16.h>
#include <cstdint>

#define NN   10000
#define EE   160000
#define FIN  1152
#define FOUT 288
#define NCK  22                 /* total (conv,k) pairs: 4+5+6+7 */
#define NCOL (NCK*FOUT)         /* 6336 */

// ---------------- device scratch ----------------------------------------------
__device__ __half g_Xh[(size_t)NN * FIN];              // fp16 x (GEMM A)
__device__ __half g_Wh[(size_t)NCOL * FIN];            // fp16 W K-major [ncol][f]
__device__ float  g_XW[(size_t)NN * NCOL];             // X@W products
__device__ float  g_P[(size_t)8 * NN * FOUT];          // Clenshaw ping-pong

__device__ int   g_deg[NN];
__device__ float g_dinv[NN];
__device__ int   g_cnt[NN];
__device__ int   g_colptr[NN + 1];
__device__ int   g_cursor[NN];
__device__ int   g_src[EE];
__device__ float g_w[EE];

// ---------------- helpers -------------------------------------------------------
__device__ __forceinline__ uint32_t smem_u32(const void* p) {
    return (uint32_t)__cvta_generic_to_shared(p);
}
__device__ __forceinline__ void cp16(uint32_t s, const void* g) {
    asm volatile("cp.async.cg.shared.global [%0], [%1], 16;"
                 :: "r"(s), "l"(__cvta_generic_to_global(g)) : "memory");
}
__device__ __forceinline__ void mma_f16(float* d, const uint32_t* a, const uint32_t* b) {
    asm volatile(
        "mma.sync.aligned.m16n8k16.row.col.f32.f16.f16.f32 "
        "{%0,%1,%2,%3}, {%4,%5,%6,%7}, {%8,%9}, {%0,%1,%2,%3};"
        : "+f"(d[0]), "+f"(d[1]), "+f"(d[2]), "+f"(d[3])
        : "r"(a[0]), "r"(a[1]), "r"(a[2]), "r"(a[3]), "r"(b[0]), "r"(b[1]));
}
__device__ __forceinline__ void ldsm4(uint32_t* r, uint32_t addr) {
    asm volatile("ldmatrix.sync.aligned.m8n8.x4.shared.b16 {%0,%1,%2,%3}, [%4];"
                 : "=r"(r[0]), "=r"(r[1]), "=r"(r[2]), "=r"(r[3]) : "r"(addr));
}
__device__ __forceinline__ void ldsm2(uint32_t* r, uint32_t addr) {
    asm volatile("ldmatrix.sync.aligned.m8n8.x2.shared.b16 {%0,%1}, [%2];"
                 : "=r"(r[0]), "=r"(r[1]) : "r"(addr));
}

// ---------------- setup kernels ------------------------------------------------
__global__ void k_zero() {
    int i = blockIdx.x * blockDim.x + threadIdx.x;
    if (i < NN) { g_deg[i] = 0; g_cnt[i] = 0; g_cursor[i] = 0; }
}
__global__ void k_hist(const int* __restrict__ ei) {
    int e = blockIdx.x * blockDim.x + threadIdx.x;
    if (e < EE) {
        atomicAdd(&g_deg[ei[e]], 1);
        atomicAdd(&g_cnt[ei[EE + e]], 1);
    }
}
__global__ void k_scan() {
    __shared__ int wsum[32];
    const int tid  = threadIdx.x;
    const int lane = tid & 31;
    const int warp = tid >> 5;

    int v[10];
    int s = 0;
#pragma unroll
    for (int i = 0; i < 10; i++) {
        int idx = tid * 10 + i;
        if (idx < NN) {
            v[i] = g_cnt[idx];
            int dg = g_deg[idx];
            g_dinv[idx] = (dg > 0) ? rsqrtf((float)dg) : 0.0f;
        } else v[i] = 0;
        s += v[i];
    }
    int inc = s;
#pragma unroll
    for (int off = 1; off < 32; off <<= 1) {
        int n = __shfl_up_sync(0xFFFFFFFF, inc, off);
        if (lane >= off) inc += n;
    }
    if (lane == 31) wsum[warp] = inc;
    __syncthreads();
    if (warp == 0) {
        int w = wsum[lane];
#pragma unroll
        for (int off = 1; off < 32; off <<= 1) {
            int n = __shfl_up_sync(0xFFFFFFFF, w, off);
            if (lane >= off) w += n;
        }
        wsum[lane] = w;
    }
    __syncthreads();
    int base = (warp > 0 ? wsum[warp - 1] : 0) + inc - s;
#pragma unroll
    for (int i = 0; i < 10; i++) {
        int idx = tid * 10 + i;
        if (idx < NN) g_colptr[idx] = base;
        base += v[i];
    }
    if (tid == 1023) g_colptr[NN] = wsum[31];
}
__global__ void k_scatter(const int* __restrict__ ei) {
    int e = blockIdx.x * blockDim.x + threadIdx.x;
    if (e < EE) {
        int r = ei[e];
        int c = ei[EE + e];
        int p = g_colptr[c] + atomicAdd(&g_cursor[c], 1);
        g_src[p] = r;
        g_w[p]   = -(g_dinv[r] * g_dinv[c]);
    }
}
__global__ void k_xh(const float* __restrict__ x) {
    const int total = NN * (FIN / 4);
    for (int idx = blockIdx.x * blockDim.x + threadIdx.x; idx < total;
         idx += gridDim.x * blockDim.x) {
        float4 v = ((const float4*)x)[idx];
        __half2* dst = (__half2*)(g_Xh + (size_t)idx * 4);
        dst[0] = __floats2half2_rn(v.x, v.y);
        dst[1] = __floats2half2_rn(v.z, v.w);
    }
}
// W[c][kk][f][o] fp32 -> g_Wh[((offs[c]+kk)*288+o)][f] fp16
__global__ void k_wt(const float* __restrict__ W0, const float* __restrict__ W1,
                     const float* __restrict__ W2, const float* __restrict__ W3) {
    __shared__ float tile[32][33];
    const int z = blockIdx.z;     // 0..21: (c,kk) pair
    int c, kk;
    if (z < 4)      { c = 0; kk = z; }
    else if (z < 9) { c = 1; kk = z - 4; }
    else if (z < 15){ c = 2; kk = z - 9; }
    else            { c = 3; kk = z - 15; }
    const float* W = (c == 0) ? W0 : (c == 1) ? W1 : (c == 2) ? W2 : W3;
    const float* Wk = W + (size_t)kk * FIN * FOUT;
    const int ncol0 = z * FOUT + blockIdx.x * 32;
    const int f0 = blockIdx.y * 32;
    const int tx = threadIdx.x, ty = threadIdx.y;
#pragma unroll
    for (int r = 0; r < 4; r++) {
        int a = ty + 8 * r;
        tile[a][tx] = Wk[(size_t)(f0 + a) * FOUT + blockIdx.x * 32 + tx];
    }
    __syncthreads();
#pragma unroll
    for (int r = 0; r < 4; r++) {
        int a = ty + 8 * r;
        g_Wh[(size_t)(ncol0 + a) * FIN + f0 + tx] = __float2half_rn(tile[tx][a]);
    }
}

// ---------------- fp16 mma.sync GEMM (256 thr, 8 warps, warp tile 32x72) ---------
#define BM 128
#define BN 144
#define BK 32
#define ASTRH 40
#define BSTRH 40
#define STAGES 5
#define A_STH (BM*ASTRH)
#define B_STH (BN*BSTRH)
#define STG_H (A_STH + B_STH)
#define SMEM_GEMM (STAGES*STG_H*2)           /* 108800 B */
#define NTILES (FIN/BK)                      /* 36 */

__global__ void __launch_bounds__(256, 2) k_gemm(
    const float* __restrict__ B0, const float* __restrict__ B1,
    const float* __restrict__ B2, const float* __restrict__ B3)
{
    extern __shared__ __align__(16) __half smp[];
    const uint32_t sbase = smem_u32(smp);

    const int m0  = blockIdx.y * BM;
    const int n0  = blockIdx.x * BN;
    const int ck = blockIdx.x >> 1;
    const float* Bv = (ck == 0) ? B0 : (ck == 4) ? B1 : (ck == 9) ? B2
                    : (ck == 15) ? B3 : nullptr;
    const int bcol0 = (blockIdx.x & 1) * BN;

    const int t   = threadIdx.x;
    const int lane = t & 31;
    const int wid  = t >> 5;
    const int warpM = wid >> 1;      // 0..3, 32 rows each
    const int warpN = wid & 1;       // 0..1, 72 cols each
    const int lq = lane >> 2;
    const int lr = lane & 3;

    // ldmatrix lane offsets (halves, within a stage)
    const int a_lm = (warpM * 32 + (lane & 7) + (lane & 8)) * ASTRH + ((lane & 16) >> 1);
    const int b_lm = (warpN * 72 + (lane & 7) + ((lane & 16) >> 1)) * BSTRH + (lane & 8);
    const int bs_lm = (warpN * 72 + 64 + (lane & 7)) * BSTRH + (lane & 8);

    // ---- staging coordinates (256 threads) ----
    // A: 512 chunks; thread handles idx t and t+256
    const int ar0 = t >> 2, ach = (t & 3) * 8;
    const __half* a_src[2];
    uint32_t a_dst[2];
#pragma unroll
    for (int i = 0; i < 2; i++) {
        int row = ar0 + 64 * i;
        int gm = m0 + row; gm = (gm < NN) ? gm : (NN - 1);
        a_src[i] = g_Xh + (size_t)gm * FIN + ach;
        a_dst[i] = sbase + (row * ASTRH + ach) * 2;
    }
    // B: 576 chunks; j = t, t+256, (512+t if t<64)
    int brow[3], bch[3];
#pragma unroll
    for (int i = 0; i < 3; i++) {
        int j = t + 256 * i;
        brow[i] = j >> 2;
        bch[i]  = (j & 3) * 8;
    }
    const bool b3 = (t < 64);
    uint32_t b_dst[3];
    const __half* b_src[3];
#pragma unroll
    for (int i = 0; i < 3; i++) {
        b_dst[i] = sbase + (A_STH + brow[i] * BSTRH + bch[i]) * 2;
        b_src[i] = g_Wh + (size_t)(n0 + brow[i]) * FIN + bch[i];
    }

    float d[2][9][4];
#pragma unroll
    for (int i = 0; i < 2; i++)
#pragma unroll
        for (int j = 0; j < 9; j++)
#pragma unroll
            for (int q = 0; q < 4; q++) d[i][j][q] = 0.f;

    // prologue: tiles 0..3 into stages 0..3
#pragma unroll
    for (int s = 0; s < STAGES - 1; s++) {
        const int k0 = s * BK;
        const uint32_t so = s * (STG_H * 2);
#pragma unroll
        for (int i = 0; i < 2; i++) cp16(a_dst[i] + so, a_src[i] + k0);
#pragma unroll
        for (int i = 0; i < 2; i++) cp16(b_dst[i] + so, b_src[i] + k0);
        if (b3) cp16(b_dst[2] + so, b_src[2] + k0);
        asm volatile("cp.async.commit_group;" ::: "memory");
    }

    for (int it = 0; it < NTILES; ++it) {
        asm volatile("cp.async.wait_group %0;" :: "n"(STAGES - 2) : "memory");
        __syncthreads();

        {
            const int ld = it + STAGES - 1;
            if (ld < NTILES) {
                const int s = ld % STAGES;
                const int k0 = ld * BK;
                const uint32_t so = s * (STG_H * 2);
#pragma unroll
                for (int i = 0; i < 2; i++) cp16(a_dst[i] + so, a_src[i] + k0);
#pragma unroll
                for (int i = 0; i < 2; i++) cp16(b_dst[i] + so, b_src[i] + k0);
                if (b3) cp16(b_dst[2] + so, b_src[2] + k0);
            }
            asm volatile("cp.async.commit_group;" ::: "memory");
        }

        const int cs = it % STAGES;
        const uint32_t sA = sbase + cs * (STG_H * 2);
        const uint32_t sB = sA + A_STH * 2;

#pragma unroll
        for (int ks = 0; ks < 2; ks++) {
            const int kb = ks * 16;
            uint32_t a[2][4], b[9][2];
#pragma unroll
            for (int mt = 0; mt < 2; mt++)
                ldsm4(a[mt], sA + (a_lm + mt * 16 * ASTRH + kb) * 2);
#pragma unroll
            for (int np = 0; np < 4; np++) {
                uint32_t r4[4];
                ldsm4(r4, sB + (b_lm + np * 16 * BSTRH + kb) * 2);
                b[2 * np][0] = r4[0]; b[2 * np][1] = r4[1];
                b[2 * np + 1][0] = r4[2]; b[2 * np + 1][1] = r4[3];
            }
            ldsm2(b[8], sB + (bs_lm + kb) * 2);
#pragma unroll
            for (int mt = 0; mt < 2; mt++)
#pragma unroll
                for (int nt = 0; nt < 9; nt++)
                    mma_f16(d[mt][nt], a[mt], b[nt]);
        }
        __syncthreads();
    }

    // epilogue -> g_XW (+bias on k==0 product columns)
#pragma unroll
    for (int mt = 0; mt < 2; mt++) {
        const int row0 = m0 + warpM * 32 + mt * 16 + lq;
        const int row1 = row0 + 8;
#pragma unroll
        for (int nt = 0; nt < 9; nt++) {
            const int col = warpN * 72 + nt * 8 + lr * 2;
            float bx = 0.f, by = 0.f;
            if (Bv) { bx = __ldg(&Bv[bcol0 + col]); by = __ldg(&Bv[bcol0 + col + 1]); }
            if (row0 < NN) {
                float2 v = make_float2(d[mt][nt][0] + bx, d[mt][nt][1] + by);
                *(float2*)&g_XW[(size_t)row0 * NCOL + n0 + col] = v;
            }
            if (row1 < NN) {
                float2 v = make_float2(d[mt][nt][2] + bx, d[mt][nt][3] + by);
                *(float2*)&g_XW[(size_t)row1 * NCOL + n0 + col] = v;
            }
        }
    }
}

// ---------------- Clenshaw step kernel (float4 per thread) -----------------------
struct CleArgs {
    const float* src[4]; int sstr4[4];
    const float* xw[4];
    const float* prv[4]; int pstr4[4];
    float*       dst[4]; int dstr4[4];
    float coef[4];
};

template <int NACT>
__global__ void __launch_bounds__(288) k_cle(CleArgs A) {
    const int node = blockIdx.x;
    const int tid  = threadIdx.x;
    const int a    = tid / 72;
    const int c4   = tid % 72;
    const bool act = (a < NACT);

    const int beg  = g_colptr[node];
    const int end  = g_colptr[node + 1];

    __shared__ int   ss[64];
    __shared__ float sw[64];

    const float4* srcp = act ? ((const float4*)A.src[a]) + c4 : nullptr;
    const int     sst4 = act ? A.sstr4[a] : 0;

    float4 acc = make_float4(0.f, 0.f, 0.f, 0.f);

    for (int b0 = beg; b0 < end; b0 += 64) {
        int cnt = min(64, end - b0);
        __syncthreads();
        if (tid < cnt) { ss[tid] = g_src[b0 + tid]; sw[tid] = g_w[b0 + tid]; }
        __syncthreads();
        if (act) {
            for (int j = 0; j < cnt; j++) {
                const float w = sw[j];
                const float4 v = srcp[(size_t)ss[j] * sst4];
                acc.x += w * v.x; acc.y += w * v.y;
                acc.z += w * v.z; acc.w += w * v.w;
            }
        }
    }

    if (act) {
        const float  cf = A.coef[a];
        const float4 x4 = ((const float4*)A.xw[a])[(size_t)node * (NCOL / 4) + c4];
        float4 v;
        v.x = x4.x + cf * acc.x; v.y = x4.y + cf * acc.y;
        v.z = x4.z + cf * acc.z; v.w = x4.w + cf * acc.w;
        if (A.prv[a]) {
            const float4 p = ((const float4*)A.prv[a])[(size_t)node * A.pstr4[a] + c4];
            v.x -= p.x; v.y -= p.y; v.z -= p.z; v.w -= p.w;
        }
        ((float4*)A.dst[a])[(size_t)node * A.dstr4[a] + c4] = v;
    }
}

// ---------------- launch --------------------------------------------------------
extern "C" void kernel_launch(void* const* d_in, const int* in_sizes, int n_in,
                              void* d_out, int out_size) {
    const float* x   = (const float*)d_in[0];
    const int*   ei  = (const int*)d_in[1];
    const float* W0  = (const float*)d_in[2];
    const float* B0v = (const float*)d_in[3];
    const float* W1  = (const float*)d_in[4];
    const float* B1v = (const float*)d_in[5];
    const float* W2  = (const float*)d_in[6];
    const float* B2v = (const float*)d_in[7];
    const float* W3  = (const float*)d_in[8];
    const float* B3v = (const float*)d_in[9];
    float* out = (float*)d_out;

    static float* pXW = nullptr;
    static float* pP  = nullptr;
    static cudaStream_t s1 = nullptr;
    static cudaEvent_t evA = nullptr, evB = nullptr;
    if (!pXW) {
        void* p;
        cudaGetSymbolAddress(&p, g_XW); pXW = (float*)p;
        cudaGetSymbolAddress(&p, g_P);  pP  = (float*)p;
        cudaFuncSetAttribute(k_gemm, cudaFuncAttributeMaxDynamicSharedMemorySize, SMEM_GEMM);
        cudaStreamCreateWithFlags(&s1, cudaStreamNonBlocking);
        cudaEventCreateWithFlags(&evA, cudaEventDisableTiming);
        cudaEventCreateWithFlags(&evB, cudaEventDisableTiming);
    }
    static const int offs[4] = {0, 4, 9, 15};
    auto XWcol = [&](int c, int kk) { return pXW + (size_t)(offs[c] + kk) * FOUT; };
    auto Pbuf  = [&](int c, int par) { return pP + (size_t)(c * 2 + par) * NN * FOUT; };

    // fork: edge preprocessing on s1 (tiny), concurrent with conversion + GEMM
    cudaEventRecord(evA, 0);
    cudaStreamWaitEvent(s1, evA, 0);
    k_zero<<<(NN + 255) / 256, 256, 0, s1>>>();
    k_hist<<<(EE + 255) / 256, 256, 0, s1>>>(ei);
    k_scan<<<1, 1024, 0, s1>>>();
    k_scatter<<<(EE + 255) / 256, 256, 0, s1>>>(ei);
    cudaEventRecord(evB, s1);

    k_xh<<<2048, 256>>>(x);
    dim3 tb(32, 8);
    k_wt<<<dim3(9, 36, NCK), tb>>>(W0, W1, W2, W3);

    dim3 gg(NCOL / BN, (NN + BM - 1) / BM);
    k_gemm<<<gg, 256, SMEM_GEMM>>>(B0v, B1v, B2v, B3v);

    // join: Clenshaw needs both GEMM results and edge structure
    cudaStreamWaitEvent(0, evB, 0);

    // Clenshaw: conv c (K=4+c) starts at t = 3-c; all finals land at t = 5
    for (int t = 0; t < 6; t++) {
        CleArgs A;
        int nact = 0;
        for (int c = 3; c >= 0; c--) {
            const int ts = 3 - c;
            if (t < ts) continue;
            const int K = 4 + c;
            const int s = t - ts;
            const int k = K - 2 - s;
            const int a = nact++;
            if (s == 0) { A.src[a] = XWcol(c, K - 1); A.sstr4[a] = NCOL / 4; }
            else        { A.src[a] = Pbuf(c, (s - 1) & 1); A.sstr4[a] = FOUT / 4; }
            if (s == 0)      { A.prv[a] = nullptr;          A.pstr4[a] = 0; }
            else if (s == 1) { A.prv[a] = XWcol(c, K - 1);  A.pstr4[a] = NCOL / 4; }
            else             { A.prv[a] = Pbuf(c, s & 1);   A.pstr4[a] = FOUT / 4; }
            if (s == K - 2) { A.dst[a] = out + c * FOUT; A.dstr4[a] = (4 * FOUT) / 4; A.coef[a] = 1.f; }
            else            { A.dst[a] = Pbuf(c, s & 1); A.dstr4[a] = FOUT / 4;       A.coef[a] = 2.f; }
            A.xw[a] = XWcol(c, k);
        }
        switch (nact) {
            case 1: k_cle<1><<<NN, 288>>>(A); break;
            case 2: k_cle<2><<<NN, 288>>>(A); break;
            case 3: k_cle<3><<<NN, 288>>>(A); break;
            default: k_cle<4><<<NN, 288>>>(A); break;
        }
    }
}

// round 15
// speedup vs baseline: 1.0744x; 1.0744x over previous
#include <cuda_runtime.h>
#include <cuda_fp16.h>
#include <cstdint>

#define NN   10000
#define EE   160000
#define FIN  1152
#define FOUT 288
#define NCK  22                 /* total (conv,k) pairs: 4+5+6+7 */
#define NCOL (NCK*FOUT)         /* 6336 */

// ---------------- device scratch ----------------------------------------------
__device__ __half g_Xh[(size_t)NN * FIN];              // fp16 x (GEMM A)
__device__ __half g_Wh[(size_t)NCOL * FIN];            // fp16 W K-major [ncol][f]
__device__ float  g_XW[(size_t)NCK * NN * FOUT];       // X@W products, z-major [z][node][288]
__device__ float  g_P[(size_t)8 * NN * FOUT];          // Clenshaw ping-pong

__device__ int   g_deg[NN];
__device__ float g_dinv[NN];
__device__ int   g_cnt[NN];
__device__ int   g_colptr[NN + 1];
__device__ int   g_cursor[NN];
__device__ int   g_src[EE];
__device__ float g_w[EE];

// ---------------- helpers -------------------------------------------------------
__device__ __forceinline__ uint32_t smem_u32(const void* p) {
    return (uint32_t)__cvta_generic_to_shared(p);
}
__device__ __forceinline__ void cp16(uint32_t s, const void* g) {
    asm volatile("cp.async.cg.shared.global [%0], [%1], 16;"
                 :: "r"(s), "l"(__cvta_generic_to_global(g)) : "memory");
}
__device__ __forceinline__ void mma_f16(float* d, const uint32_t* a, const uint32_t* b) {
    asm volatile(
        "mma.sync.aligned.m16n8k16.row.col.f32.f16.f16.f32 "
        "{%0,%1,%2,%3}, {%4,%5,%6,%7}, {%8,%9}, {%0,%1,%2,%3};"
        : "+f"(d[0]), "+f"(d[1]), "+f"(d[2]), "+f"(d[3])
        : "r"(a[0]), "r"(a[1]), "r"(a[2]), "r"(a[3]), "r"(b[0]), "r"(b[1]));
}
__device__ __forceinline__ void ldsm4(uint32_t* r, uint32_t addr) {
    asm volatile("ldmatrix.sync.aligned.m8n8.x4.shared.b16 {%0,%1,%2,%3}, [%4];"
                 : "=r"(r[0]), "=r"(r[1]), "=r"(r[2]), "=r"(r[3]) : "r"(addr));
}
__device__ __forceinline__ void ldsm2(uint32_t* r, uint32_t addr) {
    asm volatile("ldmatrix.sync.aligned.m8n8.x2.shared.b16 {%0,%1}, [%2];"
                 : "=r"(r[0]), "=r"(r[1]) : "r"(addr));
}

// ---------------- setup kernels ------------------------------------------------
__global__ void k_zero() {
    int i = blockIdx.x * blockDim.x + threadIdx.x;
    if (i < NN) { g_deg[i] = 0; g_cnt[i] = 0; g_cursor[i] = 0; }
}
__global__ void k_hist(const int* __restrict__ ei) {
    int e = blockIdx.x * blockDim.x + threadIdx.x;
    if (e < EE) {
        atomicAdd(&g_deg[ei[e]], 1);
        atomicAdd(&g_cnt[ei[EE + e]], 1);
    }
}
__global__ void k_scan() {
    __shared__ int wsum[32];
    const int tid  = threadIdx.x;
    const int lane = tid & 31;
    const int warp = tid >> 5;

    int v[10];
    int s = 0;
#pragma unroll
    for (int i = 0; i < 10; i++) {
        int idx = tid * 10 + i;
        if (idx < NN) {
            v[i] = g_cnt[idx];
            int dg = g_deg[idx];
            g_dinv[idx] = (dg > 0) ? rsqrtf((float)dg) : 0.0f;
        } else v[i] = 0;
        s += v[i];
    }
    int inc = s;
#pragma unroll
    for (int off = 1; off < 32; off <<= 1) {
        int n = __shfl_up_sync(0xFFFFFFFF, inc, off);
        if (lane >= off) inc += n;
    }
    if (lane == 31) wsum[warp] = inc;
    __syncthreads();
    if (warp == 0) {
        int w = wsum[lane];
#pragma unroll
        for (int off = 1; off < 32; off <<= 1) {
            int n = __shfl_up_sync(0xFFFFFFFF, w, off);
            if (lane >= off) w += n;
        }
        wsum[lane] = w;
    }
    __syncthreads();
    int base = (warp > 0 ? wsum[warp - 1] : 0) + inc - s;
#pragma unroll
    for (int i = 0; i < 10; i++) {
        int idx = tid * 10 + i;
        if (idx < NN) g_colptr[idx] = base;
        base += v[i];
    }
    if (tid == 1023) g_colptr[NN] = wsum[31];
}
__global__ void k_scatter(const int* __restrict__ ei) {
    int e = blockIdx.x * blockDim.x + threadIdx.x;
    if (e < EE) {
        int r = ei[e];
        int c = ei[EE + e];
        int p = g_colptr[c] + atomicAdd(&g_cursor[c], 1);
        g_src[p] = r;
        g_w[p]   = -(g_dinv[r] * g_dinv[c]);
    }
}
__global__ void k_xh(const float* __restrict__ x) {
    const int total = NN * (FIN / 4);
    for (int idx = blockIdx.x * blockDim.x + threadIdx.x; idx < total;
         idx += gridDim.x * blockDim.x) {
        float4 v = ((const float4*)x)[idx];
        __half2* dst = (__half2*)(g_Xh + (size_t)idx * 4);
        dst[0] = __floats2half2_rn(v.x, v.y);
        dst[1] = __floats2half2_rn(v.z, v.w);
    }
}
// W[c][kk][f][o] fp32 -> g_Wh[((offs[c]+kk)*288+o)][f] fp16
__global__ void k_wt(const float* __restrict__ W0, const float* __restrict__ W1,
                     const float* __restrict__ W2, const float* __restrict__ W3) {
    __shared__ float tile[32][33];
    const int z = blockIdx.z;     // 0..21: (c,kk) pair
    int c, kk;
    if (z < 4)      { c = 0; kk = z; }
    else if (z < 9) { c = 1; kk = z - 4; }
    else if (z < 15){ c = 2; kk = z - 9; }
    else            { c = 3; kk = z - 15; }
    const float* W = (c == 0) ? W0 : (c == 1) ? W1 : (c == 2) ? W2 : W3;
    const float* Wk = W + (size_t)kk * FIN * FOUT;
    const int ncol0 = z * FOUT + blockIdx.x * 32;
    const int f0 = blockIdx.y * 32;
    const int tx = threadIdx.x, ty = threadIdx.y;
#pragma unroll
    for (int r = 0; r < 4; r++) {
        int a = ty + 8 * r;
        tile[a][tx] = Wk[(size_t)(f0 + a) * FOUT + blockIdx.x * 32 + tx];
    }
    __syncthreads();
#pragma unroll
    for (int r = 0; r < 4; r++) {
        int a = ty + 8 * r;
        g_Wh[(size_t)(ncol0 + a) * FIN + f0 + tx] = __float2half_rn(tile[tx][a]);
    }
}

// ---------------- fp16 mma.sync GEMM (R12 config; z-major XW output) -------------
#define BM 128
#define BN 144
#define BK 32
#define ASTRH 40
#define BSTRH 40
#define STAGES 5
#define A_STH (BM*ASTRH)
#define B_STH (BN*BSTRH)
#define STG_H (A_STH + B_STH)
#define SMEM_GEMM (STAGES*STG_H*2)           /* 108800 B */
#define NTILES (FIN/BK)                      /* 36 */

__global__ void __launch_bounds__(128, 2) k_gemm(
    const float* __restrict__ B0, const float* __restrict__ B1,
    const float* __restrict__ B2, const float* __restrict__ B3)
{
    extern __shared__ __align__(16) __half smp[];
    const uint32_t sbase = smem_u32(smp);

    const int m0  = blockIdx.y * BM;
    const int n0  = blockIdx.x * BN;
    const int z   = blockIdx.x >> 1;
    const float* Bv = (z == 0) ? B0 : (z == 4) ? B1 : (z == 9) ? B2
                    : (z == 15) ? B3 : nullptr;
    const int bcol0 = (blockIdx.x & 1) * BN;
    float* xwz = g_XW + (size_t)z * NN * FOUT;   // z-major block

    const int t   = threadIdx.x;
    const int lane = t & 31;
    const int wid  = t >> 5;
    const int warpM = wid >> 1;
    const int warpN = wid & 1;
    const int lq = lane >> 2;
    const int lr = lane & 3;

    const int a_lm = (warpM * 64 + (lane & 7) + (lane & 8)) * ASTRH + ((lane & 16) >> 1);
    const int b_lm = (warpN * 72 + (lane & 7) + ((lane & 16) >> 1)) * BSTRH + (lane & 8);
    const int bs_lm = (warpN * 72 + 64 + (lane & 7)) * BSTRH + (lane & 8);

    const int ar0 = t >> 2, ach = (t & 3) * 8;
    const __half* a_src[4];
    uint32_t a_dst[4];
#pragma unroll
    for (int i = 0; i < 4; i++) {
        int row = ar0 + 32 * i;
        int gm = m0 + row; gm = (gm < NN) ? gm : (NN - 1);
        a_src[i] = g_Xh + (size_t)gm * FIN + ach;
        a_dst[i] = sbase + (row * ASTRH + ach) * 2;
    }
    int brow[5], bch[5];
#pragma unroll
    for (int i = 0; i < 5; i++) {
        int j = t + 128 * i;
        brow[i] = j >> 2;
        bch[i]  = (j & 3) * 8;
    }
    const bool b5 = (t < 64);
    uint32_t b_dst[5];
    const __half* b_src[5];
#pragma unroll
    for (int i = 0; i < 5; i++) {
        b_dst[i] = sbase + (A_STH + brow[i] * BSTRH + bch[i]) * 2;
        b_src[i] = g_Wh + (size_t)(n0 + brow[i]) * FIN + bch[i];
    }

    float d[4][9][4];
#pragma unroll
    for (int i = 0; i < 4; i++)
#pragma unroll
        for (int j = 0; j < 9; j++)
#pragma unroll
            for (int q = 0; q < 4; q++) d[i][j][q] = 0.f;

#pragma unroll
    for (int s = 0; s < STAGES - 1; s++) {
        const int k0 = s * BK;
        const uint32_t so = s * (STG_H * 2);
#pragma unroll
        for (int i = 0; i < 4; i++) cp16(a_dst[i] + so, a_src[i] + k0);
#pragma unroll
        for (int i = 0; i < 4; i++) cp16(b_dst[i] + so, b_src[i] + k0);
        if (b5) cp16(b_dst[4] + so, b_src[4] + k0);
        asm volatile("cp.async.commit_group;" ::: "memory");
    }

    uint32_t af[2][4][4], bf[2][9][2];

    asm volatile("cp.async.wait_group %0;" :: "n"(STAGES - 3) : "memory");
    __syncthreads();
    {
        const uint32_t sA = sbase;
        const uint32_t sB = sbase + A_STH * 2;
#pragma unroll
        for (int mt = 0; mt < 4; mt++)
            ldsm4(af[0][mt], sA + (a_lm + mt * 16 * ASTRH) * 2);
#pragma unroll
        for (int np = 0; np < 4; np++) {
            uint32_t r4[4];
            ldsm4(r4, sB + (b_lm + np * 16 * BSTRH) * 2);
            bf[0][2 * np][0] = r4[0]; bf[0][2 * np][1] = r4[1];
            bf[0][2 * np + 1][0] = r4[2]; bf[0][2 * np + 1][1] = r4[3];
        }
        ldsm2(bf[0][8], sB + bs_lm * 2);
    }

    for (int it = 0; it < NTILES; ++it) {
        if (it > 0) {
            asm volatile("cp.async.wait_group %0;" :: "n"(STAGES - 3) : "memory");
            __syncthreads();
        }
        {
            const int ld = it + STAGES - 1;
            if (ld < NTILES) {
                const int s = ld % STAGES;
                const int k0 = ld * BK;
                const uint32_t so = s * (STG_H * 2);
#pragma unroll
                for (int i = 0; i < 4; i++) cp16(a_dst[i] + so, a_src[i] + k0);
#pragma unroll
                for (int i = 0; i < 4; i++) cp16(b_dst[i] + so, b_src[i] + k0);
                if (b5) cp16(b_dst[4] + so, b_src[4] + k0);
            }
            asm volatile("cp.async.commit_group;" ::: "memory");
        }

        const int cs = it % STAGES;
        const uint32_t sA = sbase + cs * (STG_H * 2);
        const uint32_t sB = sA + A_STH * 2;

#pragma unroll
        for (int mt = 0; mt < 4; mt++)
            ldsm4(af[1][mt], sA + (a_lm + mt * 16 * ASTRH + 16) * 2);
#pragma unroll
        for (int np = 0; np < 4; np++) {
            uint32_t r4[4];
            ldsm4(r4, sB + (b_lm + np * 16 * BSTRH + 16) * 2);
            bf[1][2 * np][0] = r4[0]; bf[1][2 * np][1] = r4[1];
            bf[1][2 * np + 1][0] = r4[2]; bf[1][2 * np + 1][1] = r4[3];
        }
        ldsm2(bf[1][8], sB + (bs_lm + 16) * 2);
#pragma unroll
        for (int mt = 0; mt < 4; mt++)
#pragma unroll
            for (int nt = 0; nt < 9; nt++)
                mma_f16(d[mt][nt], af[0][mt], bf[0][nt]);

        if (it + 1 < NTILES) {
            const int ns = (it + 1) % STAGES;
            const uint32_t nA = sbase + ns * (STG_H * 2);
            const uint32_t nB = nA + A_STH * 2;
#pragma unroll
            for (int mt = 0; mt < 4; mt++)
                ldsm4(af[0][mt], nA + (a_lm + mt * 16 * ASTRH) * 2);
#pragma unroll
            for (int np = 0; np < 4; np++) {
                uint32_t r4[4];
                ldsm4(r4, nB + (b_lm + np * 16 * BSTRH) * 2);
                bf[0][2 * np][0] = r4[0]; bf[0][2 * np][1] = r4[1];
                bf[0][2 * np + 1][0] = r4[2]; bf[0][2 * np + 1][1] = r4[3];
            }
            ldsm2(bf[0][8], nB + bs_lm * 2);
        }
#pragma unroll
        for (int mt = 0; mt < 4; mt++)
#pragma unroll
            for (int nt = 0; nt < 9; nt++)
                mma_f16(d[mt][nt], af[1][mt], bf[1][nt]);
    }

    // epilogue -> z-major XW (+bias on k==0 product columns)
#pragma unroll
    for (int mt = 0; mt < 4; mt++) {
        const int row0 = m0 + warpM * 64 + mt * 16 + lq;
        const int row1 = row0 + 8;
#pragma unroll
        for (int nt = 0; nt < 9; nt++) {
            const int col = bcol0 + warpN * 72 + nt * 8 + lr * 2;
            float bx = 0.f, by = 0.f;
            if (Bv) { bx = __ldg(&Bv[col]); by = __ldg(&Bv[col + 1]); }
            if (row0 < NN) {
                float2 v = make_float2(d[mt][nt][0] + bx, d[mt][nt][1] + by);
                *(float2*)&xwz[(size_t)row0 * FOUT + col] = v;
            }
            if (row1 < NN) {
                float2 v = make_float2(d[mt][nt][2] + bx, d[mt][nt][3] + by);
                *(float2*)&xwz[(size_t)row1 * FOUT + col] = v;
            }
        }
    }
}

// ---------------- Clenshaw step kernel (float4, uniform stride-288 buffers) ------
struct CleArgs {
    const float* src[4];                       // node stride FOUT
    const float* xw[4];                        // node stride FOUT
    const float* prv[4];                       // node stride FOUT; null -> zero
    float*       dst[4]; int dstr4[4];         // finals have stride 4*FOUT
    float coef[4];
};

// 288 threads: thread t -> (chain a = t/72, col4 = t%72); one float4/thread/edge.
template <int NACT>
__global__ void __launch_bounds__(288) k_cle(CleArgs A) {
    const int node = blockIdx.x;
    const int tid  = threadIdx.x;
    const int a    = tid / 72;
    const int c4   = tid % 72;
    const bool act = (a < NACT);

    const int beg  = g_colptr[node];
    const int end  = g_colptr[node + 1];

    __shared__ int   ss[64];
    __shared__ float sw[64];

    const float4* srcp = act ? ((const float4*)A.src[a]) + c4 : nullptr;

    float4 acc = make_float4(0.f, 0.f, 0.f, 0.f);

    for (int b0 = beg; b0 < end; b0 += 64) {
        int cnt = min(64, end - b0);
        __syncthreads();
        if (tid < cnt) { ss[tid] = g_src[b0 + tid]; sw[tid] = g_w[b0 + tid]; }
        __syncthreads();
        if (act) {
            for (int j = 0; j < cnt; j++) {
                const float w = sw[j];
                const float4 v = srcp[(size_t)ss[j] * (FOUT / 4)];
                acc.x += w * v.x; acc.y += w * v.y;
                acc.z += w * v.z; acc.w += w * v.w;
            }
        }
    }

    if (act) {
        const float  cf = A.coef[a];
        const float4 x4 = ((const float4*)A.xw[a])[(size_t)node * (FOUT / 4) + c4];
        float4 v;
        v.x = x4.x + cf * acc.x; v.y = x4.y + cf * acc.y;
        v.z = x4.z + cf * acc.z; v.w = x4.w + cf * acc.w;
        if (A.prv[a]) {
            const float4 p = ((const float4*)A.prv[a])[(size_t)node * (FOUT / 4) + c4];
            v.x -= p.x; v.y -= p.y; v.z -= p.z; v.w -= p.w;
        }
        ((float4*)A.dst[a])[(size_t)node * A.dstr4[a] + c4] = v;
    }
}

// ---------------- launch --------------------------------------------------------
extern "C" void kernel_launch(void* const* d_in, const int* in_sizes, int n_in,
                              void* d_out, int out_size) {
    const float* x   = (const float*)d_in[0];
    const int*   ei  = (const int*)d_in[1];
    const float* W0  = (const float*)d_in[2];
    const float* B0v = (const float*)d_in[3];
    const float* W1  = (const float*)d_in[4];
    const float* B1v = (const float*)d_in[5];
    const float* W2  = (const float*)d_in[6];
    const float* B2v = (const float*)d_in[7];
    const float* W3  = (const float*)d_in[8];
    const float* B3v = (const float*)d_in[9];
    float* out = (float*)d_out;

    static float* pXW = nullptr;
    static float* pP  = nullptr;
    static cudaStream_t s1 = nullptr;
    static cudaEvent_t evA = nullptr, evB = nullptr;
    if (!pXW) {
        void* p;
        cudaGetSymbolAddress(&p, g_XW); pXW = (float*)p;
        cudaGetSymbolAddress(&p, g_P);  pP  = (float*)p;
        cudaFuncSetAttribute(k_gemm, cudaFuncAttributeMaxDynamicSharedMemorySize, SMEM_GEMM);
        cudaStreamCreateWithFlags(&s1, cudaStreamNonBlocking);
        cudaEventCreateWithFlags(&evA, cudaEventDisableTiming);
        cudaEventCreateWithFlags(&evB, cudaEventDisableTiming);
    }
    static const int offs[4] = {0, 4, 9, 15};
    auto XWcol = [&](int c, int kk) { return pXW + (size_t)(offs[c] + kk) * NN * FOUT; };
    auto Pbuf  = [&](int c, int par) { return pP + (size_t)(c * 2 + par) * NN * FOUT; };

    // fork: edge preprocessing on s1 (tiny), concurrent with conversion + GEMM
    cudaEventRecord(evA, 0);
    cudaStreamWaitEvent(s1, evA, 0);
    k_zero<<<(NN + 255) / 256, 256, 0, s1>>>();
    k_hist<<<(EE + 255) / 256, 256, 0, s1>>>(ei);
    k_scan<<<1, 1024, 0, s1>>>();
    k_scatter<<<(EE + 255) / 256, 256, 0, s1>>>(ei);
    cudaEventRecord(evB, s1);

    k_xh<<<2048, 256>>>(x);
    dim3 tb(32, 8);
    k_wt<<<dim3(9, 36, NCK), tb>>>(W0, W1, W2, W3);

    dim3 gg(NCOL / BN, (NN + BM - 1) / BM);
    k_gemm<<<gg, 128, SMEM_GEMM>>>(B0v, B1v, B2v, B3v);

    // join: Clenshaw needs both GEMM results and edge structure
    cudaStreamWaitEvent(0, evB, 0);

    // Clenshaw: conv c (K=4+c) starts at t = 3-c; all finals land at t = 5
    for (int t = 0; t < 6; t++) {
        CleArgs A;
        int nact = 0;
        for (int c = 3; c >= 0; c--) {
            const int ts = 3 - c;
            if (t < ts) continue;
            const int K = 4 + c;
            const int s = t - ts;
            const int k = K - 2 - s;
            const int a = nact++;
            if (s == 0) A.src[a] = XWcol(c, K - 1);
            else        A.src[a] = Pbuf(c, (s - 1) & 1);
            if (s == 0)      A.prv[a] = nullptr;
            else if (s == 1) A.prv[a] = XWcol(c, K - 1);
            else             A.prv[a] = Pbuf(c, s & 1);
            if (s == K - 2) { A.dst[a] = out + c * FOUT; A.dstr4[a] = (4 * FOUT) / 4; A.coef[a] = 1.f; }
            else            { A.dst[a] = Pbuf(c, s & 1); A.dstr4[a] = FOUT / 4;       A.coef[a] = 2.f; }
            A.xw[a] = XWcol(c, k);
        }
        switch (nact) {
            case 1: k_cle<1><<<NN, 288>>>(A); break;
            case 2: k_cle<2><<<NN, 288>>>(A); break;
            case 3: k_cle<3><<<NN, 288>>>(A); break;
            default: k_cle<4><<<NN, 288>>>(A); break;
        }
    }
}

// round 16
// speedup vs baseline: 1.1940x; 1.1113x over previous
#include <cuda_runtime.h>
#include <cuda_fp16.h>
#include <cstdint>

#define NN   10000
#define EE   160000
#define FIN  1152
#define FOUT 288
#define NCK  22                 /* total (conv,k) pairs: 4+5+6+7 */
#define NCOL (NCK*FOUT)         /* 6336 */

// ---------------- device scratch ----------------------------------------------
__device__ __half g_Xh[(size_t)NN * FIN];              // fp16 x (GEMM A)
__device__ __half g_Wh[(size_t)NCOL * FIN];            // fp16 W K-major [ncol][f]
__device__ float  g_XW[(size_t)NCK * NN * FOUT];       // X@W products, z-major
__device__ __half g_XWh[(size_t)4 * NN * FOUT];        // fp16 shadow of top-k slabs
__device__ float  g_P[(size_t)8 * NN * FOUT];          // Clenshaw ping-pong (fp32)
__device__ __half g_Ph[(size_t)8 * NN * FOUT];         // fp16 shadow (gather source)

__device__ int   g_deg[NN];
__device__ float g_dinv[NN];
__device__ int   g_cnt[NN];
__device__ int   g_colptr[NN + 1];
__device__ int   g_cursor[NN];
__device__ int   g_src[EE];
__device__ float g_w[EE];

// ---------------- helpers -------------------------------------------------------
__device__ __forceinline__ uint32_t smem_u32(const void* p) {
    return (uint32_t)__cvta_generic_to_shared(p);
}
__device__ __forceinline__ void cp16(uint32_t s, const void* g) {
    asm volatile("cp.async.cg.shared.global [%0], [%1], 16;"
                 :: "r"(s), "l"(__cvta_generic_to_global(g)) : "memory");
}
__device__ __forceinline__ void mma_f16(float* d, const uint32_t* a, const uint32_t* b) {
    asm volatile(
        "mma.sync.aligned.m16n8k16.row.col.f32.f16.f16.f32 "
        "{%0,%1,%2,%3}, {%4,%5,%6,%7}, {%8,%9}, {%0,%1,%2,%3};"
        : "+f"(d[0]), "+f"(d[1]), "+f"(d[2]), "+f"(d[3])
        : "r"(a[0]), "r"(a[1]), "r"(a[2]), "r"(a[3]), "r"(b[0]), "r"(b[1]));
}
__device__ __forceinline__ void ldsm4(uint32_t* r, uint32_t addr) {
    asm volatile("ldmatrix.sync.aligned.m8n8.x4.shared.b16 {%0,%1,%2,%3}, [%4];"
                 : "=r"(r[0]), "=r"(r[1]), "=r"(r[2]), "=r"(r[3]) : "r"(addr));
}
__device__ __forceinline__ void ldsm2(uint32_t* r, uint32_t addr) {
    asm volatile("ldmatrix.sync.aligned.m8n8.x2.shared.b16 {%0,%1}, [%2];"
                 : "=r"(r[0]), "=r"(r[1]) : "r"(addr));
}

// ---------------- setup kernels ------------------------------------------------
__global__ void k_zero() {
    int i = blockIdx.x * blockDim.x + threadIdx.x;
    if (i < NN) { g_deg[i] = 0; g_cnt[i] = 0; g_cursor[i] = 0; }
}
__global__ void k_hist(const int* __restrict__ ei) {
    int e = blockIdx.x * blockDim.x + threadIdx.x;
    if (e < EE) {
        atomicAdd(&g_deg[ei[e]], 1);
        atomicAdd(&g_cnt[ei[EE + e]], 1);
    }
}
__global__ void k_scan() {
    __shared__ int wsum[32];
    const int tid  = threadIdx.x;
    const int lane = tid & 31;
    const int warp = tid >> 5;

    int v[10];
    int s = 0;
#pragma unroll
    for (int i = 0; i < 10; i++) {
        int idx = tid * 10 + i;
        if (idx < NN) {
            v[i] = g_cnt[idx];
            int dg = g_deg[idx];
            g_dinv[idx] = (dg > 0) ? rsqrtf((float)dg) : 0.0f;
        } else v[i] = 0;
        s += v[i];
    }
    int inc = s;
#pragma unroll
    for (int off = 1; off < 32; off <<= 1) {
        int n = __shfl_up_sync(0xFFFFFFFF, inc, off);
        if (lane >= off) inc += n;
    }
    if (lane == 31) wsum[warp] = inc;
    __syncthreads();
    if (warp == 0) {
        int w = wsum[lane];
#pragma unroll
        for (int off = 1; off < 32; off <<= 1) {
            int n = __shfl_up_sync(0xFFFFFFFF, w, off);
            if (lane >= off) w += n;
        }
        wsum[lane] = w;
    }
    __syncthreads();
    int base = (warp > 0 ? wsum[warp - 1] : 0) + inc - s;
#pragma unroll
    for (int i = 0; i < 10; i++) {
        int idx = tid * 10 + i;
        if (idx < NN) g_colptr[idx] = base;
        base += v[i];
    }
    if (tid == 1023) g_colptr[NN] = wsum[31];
}
__global__ void k_scatter(const int* __restrict__ ei) {
    int e = blockIdx.x * blockDim.x + threadIdx.x;
    if (e < EE) {
        int r = ei[e];
        int c = ei[EE + e];
        int p = g_colptr[c] + atomicAdd(&g_cursor[c], 1);
        g_src[p] = r;
        g_w[p]   = -(g_dinv[r] * g_dinv[c]);
    }
}
__global__ void k_xh(const float* __restrict__ x) {
    const int total = NN * (FIN / 4);
    for (int idx = blockIdx.x * blockDim.x + threadIdx.x; idx < total;
         idx += gridDim.x * blockDim.x) {
        float4 v = ((const float4*)x)[idx];
        __half2* dst = (__half2*)(g_Xh + (size_t)idx * 4);
        dst[0] = __floats2half2_rn(v.x, v.y);
        dst[1] = __floats2half2_rn(v.z, v.w);
    }
}
// W[c][kk][f][o] fp32 -> g_Wh[((offs[c]+kk)*288+o)][f] fp16
__global__ void k_wt(const float* __restrict__ W0, const float* __restrict__ W1,
                     const float* __restrict__ W2, const float* __restrict__ W3) {
    __shared__ float tile[32][33];
    const int z = blockIdx.z;
    int c, kk;
    if (z < 4)      { c = 0; kk = z; }
    else if (z < 9) { c = 1; kk = z - 4; }
    else if (z < 15){ c = 2; kk = z - 9; }
    else            { c = 3; kk = z - 15; }
    const float* W = (c == 0) ? W0 : (c == 1) ? W1 : (c == 2) ? W2 : W3;
    const float* Wk = W + (size_t)kk * FIN * FOUT;
    const int ncol0 = z * FOUT + blockIdx.x * 32;
    const int f0 = blockIdx.y * 32;
    const int tx = threadIdx.x, ty = threadIdx.y;
#pragma unroll
    for (int r = 0; r < 4; r++) {
        int a = ty + 8 * r;
        tile[a][tx] = Wk[(size_t)(f0 + a) * FOUT + blockIdx.x * 32 + tx];
    }
    __syncthreads();
#pragma unroll
    for (int r = 0; r < 4; r++) {
        int a = ty + 8 * r;
        g_Wh[(size_t)(ncol0 + a) * FIN + f0 + tx] = __float2half_rn(tile[tx][a]);
    }
}

// ---------------- fp16 mma.sync GEMM (z-major XW; fp16 shadow for top-k) ---------
#define BM 128
#define BN 144
#define BK 32
#define ASTRH 40
#define BSTRH 40
#define STAGES 5
#define A_STH (BM*ASTRH)
#define B_STH (BN*BSTRH)
#define STG_H (A_STH + B_STH)
#define SMEM_GEMM (STAGES*STG_H*2)           /* 108800 B */
#define NTILES (FIN/BK)                      /* 36 */

__global__ void __launch_bounds__(128, 2) k_gemm(
    const float* __restrict__ B0, const float* __restrict__ B1,
    const float* __restrict__ B2, const float* __restrict__ B3)
{
    extern __shared__ __align__(16) __half smp[];
    const uint32_t sbase = smem_u32(smp);

    const int m0  = blockIdx.y * BM;
    const int n0  = blockIdx.x * BN;
    const int z   = blockIdx.x >> 1;
    const float* Bv = (z == 0) ? B0 : (z == 4) ? B1 : (z == 9) ? B2
                    : (z == 15) ? B3 : nullptr;
    const int bcol0 = (blockIdx.x & 1) * BN;
    float* xwz = g_XW + (size_t)z * NN * FOUT;
    // fp16 shadow for top-k slabs (z = offs[c]+K-1)
    const int tc = (z == 3) ? 0 : (z == 8) ? 1 : (z == 14) ? 2 : (z == 21) ? 3 : -1;
    __half* xwh = (tc >= 0) ? g_XWh + (size_t)tc * NN * FOUT : nullptr;

    const int t   = threadIdx.x;
    const int lane = t & 31;
    const int wid  = t >> 5;
    const int warpM = wid >> 1;
    const int warpN = wid & 1;
    const int lq = lane >> 2;
    const int lr = lane & 3;

    const int a_lm = (warpM * 64 + (lane & 7) + (lane & 8)) * ASTRH + ((lane & 16) >> 1);
    const int b_lm = (warpN * 72 + (lane & 7) + ((lane & 16) >> 1)) * BSTRH + (lane & 8);
    const int bs_lm = (warpN * 72 + 64 + (lane & 7)) * BSTRH + (lane & 8);

    const int ar0 = t >> 2, ach = (t & 3) * 8;
    const __half* a_src[4];
    uint32_t a_dst[4];
#pragma unroll
    for (int i = 0; i < 4; i++) {
        int row = ar0 + 32 * i;
        int gm = m0 + row; gm = (gm < NN) ? gm : (NN - 1);
        a_src[i] = g_Xh + (size_t)gm * FIN + ach;
        a_dst[i] = sbase + (row * ASTRH + ach) * 2;
    }
    int brow[5], bch[5];
#pragma unroll
    for (int i = 0; i < 5; i++) {
        int j = t + 128 * i;
        brow[i] = j >> 2;
        bch[i]  = (j & 3) * 8;
    }
    const bool b5 = (t < 64);
    uint32_t b_dst[5];
    const __half* b_src[5];
#pragma unroll
    for (int i = 0; i < 5; i++) {
        b_dst[i] = sbase + (A_STH + brow[i] * BSTRH + bch[i]) * 2;
        b_src[i] = g_Wh + (size_t)(n0 + brow[i]) * FIN + bch[i];
    }

    float d[4][9][4];
#pragma unroll
    for (int i = 0; i < 4; i++)
#pragma unroll
        for (int j = 0; j < 9; j++)
#pragma unroll
            for (int q = 0; q < 4; q++) d[i][j][q] = 0.f;

#pragma unroll
    for (int s = 0; s < STAGES - 1; s++) {
        const int k0 = s * BK;
        const uint32_t so = s * (STG_H * 2);
#pragma unroll
        for (int i = 0; i < 4; i++) cp16(a_dst[i] + so, a_src[i] + k0);
#pragma unroll
        for (int i = 0; i < 4; i++) cp16(b_dst[i] + so, b_src[i] + k0);
        if (b5) cp16(b_dst[4] + so, b_src[4] + k0);
        asm volatile("cp.async.commit_group;" ::: "memory");
    }

    uint32_t af[2][4][4], bf[2][9][2];

    asm volatile("cp.async.wait_group %0;" :: "n"(STAGES - 3) : "memory");
    __syncthreads();
    {
        const uint32_t sA = sbase;
        const uint32_t sB = sbase + A_STH * 2;
#pragma unroll
        for (int mt = 0; mt < 4; mt++)
            ldsm4(af[0][mt], sA + (a_lm + mt * 16 * ASTRH) * 2);
#pragma unroll
        for (int np = 0; np < 4; np++) {
            uint32_t r4[4];
            ldsm4(r4, sB + (b_lm + np * 16 * BSTRH) * 2);
            bf[0][2 * np][0] = r4[0]; bf[0][2 * np][1] = r4[1];
            bf[0][2 * np + 1][0] = r4[2]; bf[0][2 * np + 1][1] = r4[3];
        }
        ldsm2(bf[0][8], sB + bs_lm * 2);
    }

    for (int it = 0; it < NTILES; ++it) {
        if (it > 0) {
            asm volatile("cp.async.wait_group %0;" :: "n"(STAGES - 3) : "memory");
            __syncthreads();
        }
        {
            const int ld = it + STAGES - 1;
            if (ld < NTILES) {
                const int s = ld % STAGES;
                const int k0 = ld * BK;
                const uint32_t so = s * (STG_H * 2);
#pragma unroll
                for (int i = 0; i < 4; i++) cp16(a_dst[i] + so, a_src[i] + k0);
#pragma unroll
                for (int i = 0; i < 4; i++) cp16(b_dst[i] + so, b_src[i] + k0);
                if (b5) cp16(b_dst[4] + so, b_src[4] + k0);
            }
            asm volatile("cp.async.commit_group;" ::: "memory");
        }

        const int cs = it % STAGES;
        const uint32_t sA = sbase + cs * (STG_H * 2);
        const uint32_t sB = sA + A_STH * 2;

#pragma unroll
        for (int mt = 0; mt < 4; mt++)
            ldsm4(af[1][mt], sA + (a_lm + mt * 16 * ASTRH + 16) * 2);
#pragma unroll
        for (int np = 0; np < 4; np++) {
            uint32_t r4[4];
            ldsm4(r4, sB + (b_lm + np * 16 * BSTRH + 16) * 2);
            bf[1][2 * np][0] = r4[0]; bf[1][2 * np][1] = r4[1];
            bf[1][2 * np + 1][0] = r4[2]; bf[1][2 * np + 1][1] = r4[3];
        }
        ldsm2(bf[1][8], sB + (bs_lm + 16) * 2);
#pragma unroll
        for (int mt = 0; mt < 4; mt++)
#pragma unroll
            for (int nt = 0; nt < 9; nt++)
                mma_f16(d[mt][nt], af[0][mt], bf[0][nt]);

        if (it + 1 < NTILES) {
            const int ns = (it + 1) % STAGES;
            const uint32_t nA = sbase + ns * (STG_H * 2);
            const uint32_t nB = nA + A_STH * 2;
#pragma unroll
            for (int mt = 0; mt < 4; mt++)
                ldsm4(af[0][mt], nA + (a_lm + mt * 16 * ASTRH) * 2);
#pragma unroll
            for (int np = 0; np < 4; np++) {
                uint32_t r4[4];
                ldsm4(r4, nB + (b_lm + np * 16 * BSTRH) * 2);
                bf[0][2 * np][0] = r4[0]; bf[0][2 * np][1] = r4[1];
                bf[0][2 * np + 1][0] = r4[2]; bf[0][2 * np + 1][1] = r4[3];
            }
            ldsm2(bf[0][8], nB + bs_lm * 2);
        }
#pragma unroll
        for (int mt = 0; mt < 4; mt++)
#pragma unroll
            for (int nt = 0; nt < 9; nt++)
                mma_f16(d[mt][nt], af[1][mt], bf[1][nt]);
    }

    // epilogue -> z-major XW (+bias), plus fp16 shadow for top-k slabs
#pragma unroll
    for (int mt = 0; mt < 4; mt++) {
        const int row0 = m0 + warpM * 64 + mt * 16 + lq;
        const int row1 = row0 + 8;
#pragma unroll
        for (int nt = 0; nt < 9; nt++) {
            const int col = bcol0 + warpN * 72 + nt * 8 + lr * 2;
            float bx = 0.f, by = 0.f;
            if (Bv) { bx = __ldg(&Bv[col]); by = __ldg(&Bv[col + 1]); }
            if (row0 < NN) {
                float2 v = make_float2(d[mt][nt][0] + bx, d[mt][nt][1] + by);
                *(float2*)&xwz[(size_t)row0 * FOUT + col] = v;
                if (xwh) *(__half2*)&xwh[(size_t)row0 * FOUT + col] = __floats2half2_rn(v.x, v.y);
            }
            if (row1 < NN) {
                float2 v = make_float2(d[mt][nt][2] + bx, d[mt][nt][3] + by);
                *(float2*)&xwz[(size_t)row1 * FOUT + col] = v;
                if (xwh) *(__half2*)&xwh[(size_t)row1 * FOUT + col] = __floats2half2_rn(v.x, v.y);
            }
        }
    }
}

// ---------------- Clenshaw step kernel (fp16 gathers, fp32 state) ----------------
struct CleArgs {
    const __half* srcH[4];                     // fp16 gather source, node stride FOUT
    const float*  xw[4];                       // fp32, node stride FOUT
    const float*  prv[4];                      // fp32; null -> zero
    float*        dst[4]; int dstr4[4];        // fp32 out (finals stride 4*FOUT)
    __half*       dstH[4];                     // fp16 shadow; null for finals
    float coef[4];
};

// 288 threads: thread t -> (chain a = t/72, col4 = t%72); uint2 (4 halves)/edge.
template <int NACT>
__global__ void __launch_bounds__(288) k_cle(CleArgs A) {
    const int node = blockIdx.x;
    const int tid  = threadIdx.x;
    const int a    = tid / 72;
    const int c4   = tid % 72;
    const bool act = (a < NACT);

    const int beg  = g_colptr[node];
    const int end  = g_colptr[node + 1];

    __shared__ int   ss[64];
    __shared__ float sw[64];

    const __half* srcp = act ? (A.srcH[a] + c4 * 4) : nullptr;

    float4 acc = make_float4(0.f, 0.f, 0.f, 0.f);

    for (int b0 = beg; b0 < end; b0 += 64) {
        int cnt = min(64, end - b0);
        __syncthreads();
        if (tid < cnt) { ss[tid] = g_src[b0 + tid]; sw[tid] = g_w[b0 + tid]; }
        __syncthreads();
        if (act) {
            for (int j = 0; j < cnt; j++) {
                const float w = sw[j];
                uint2 u = *(const uint2*)(srcp + (size_t)ss[j] * FOUT);
                float2 f01 = __half22float2(*(__half2*)&u.x);
                float2 f23 = __half22float2(*(__half2*)&u.y);
                acc.x += w * f01.x; acc.y += w * f01.y;
                acc.z += w * f23.x; acc.w += w * f23.y;
            }
        }
    }

    if (act) {
        const float  cf = A.coef[a];
        const float4 x4 = ((const float4*)A.xw[a])[(size_t)node * (FOUT / 4) + c4];
        float4 v;
        v.x = x4.x + cf * acc.x; v.y = x4.y + cf * acc.y;
        v.z = x4.z + cf * acc.z; v.w = x4.w + cf * acc.w;
        if (A.prv[a]) {
            const float4 p = ((const float4*)A.prv[a])[(size_t)node * (FOUT / 4) + c4];
            v.x -= p.x; v.y -= p.y; v.z -= p.z; v.w -= p.w;
        }
        ((float4*)A.dst[a])[(size_t)node * A.dstr4[a] + c4] = v;
        if (A.dstH[a]) {
            uint2 h;
            *(__half2*)&h.x = __floats2half2_rn(v.x, v.y);
            *(__half2*)&h.y = __floats2half2_rn(v.z, v.w);
            *(uint2*)(A.dstH[a] + (size_t)node * FOUT + c4 * 4) = h;
        }
    }
}

// ---------------- launch --------------------------------------------------------
extern "C" void kernel_launch(void* const* d_in, const int* in_sizes, int n_in,
                              void* d_out, int out_size) {
    const float* x   = (const float*)d_in[0];
    const int*   ei  = (const int*)d_in[1];
    const float* W0  = (const float*)d_in[2];
    const float* B0v = (const float*)d_in[3];
    const float* W1  = (const float*)d_in[4];
    const float* B1v = (const float*)d_in[5];
    const float* W2  = (const float*)d_in[6];
    const float* B2v = (const float*)d_in[7];
    const float* W3  = (const float*)d_in[8];
    const float* B3v = (const float*)d_in[9];
    float* out = (float*)d_out;

    static float*  pXW  = nullptr;
    static float*  pP   = nullptr;
    static __half* pXWh = nullptr;
    static __half* pPh  = nullptr;
    static cudaStream_t s1 = nullptr;
    static cudaEvent_t evA = nullptr, evB = nullptr;
    if (!pXW) {
        void* p;
        cudaGetSymbolAddress(&p, g_XW);  pXW  = (float*)p;
        cudaGetSymbolAddress(&p, g_P);   pP   = (float*)p;
        cudaGetSymbolAddress(&p, g_XWh); pXWh = (__half*)p;
        cudaGetSymbolAddress(&p, g_Ph);  pPh  = (__half*)p;
        cudaFuncSetAttribute(k_gemm, cudaFuncAttributeMaxDynamicSharedMemorySize, SMEM_GEMM);
        cudaStreamCreateWithFlags(&s1, cudaStreamNonBlocking);
        cudaEventCreateWithFlags(&evA, cudaEventDisableTiming);
        cudaEventCreateWithFlags(&evB, cudaEventDisableTiming);
    }
    static const int offs[4] = {0, 4, 9, 15};
    auto XWcol  = [&](int c, int kk) { return pXW + (size_t)(offs[c] + kk) * NN * FOUT; };
    auto XWcolH = [&](int c) { return pXWh + (size_t)c * NN * FOUT; };
    auto Pbuf   = [&](int c, int par) { return pP + (size_t)(c * 2 + par) * NN * FOUT; };
    auto PbufH  = [&](int c, int par) { return pPh + (size_t)(c * 2 + par) * NN * FOUT; };

    // fork: edge preprocessing on s1 (tiny), concurrent with conversion + GEMM
    cudaEventRecord(evA, 0);
    cudaStreamWaitEvent(s1, evA, 0);
    k_zero<<<(NN + 255) / 256, 256, 0, s1>>>();
    k_hist<<<(EE + 255) / 256, 256, 0, s1>>>(ei);
    k_scan<<<1, 1024, 0, s1>>>();
    k_scatter<<<(EE + 255) / 256, 256, 0, s1>>>(ei);
    cudaEventRecord(evB, s1);

    k_xh<<<2048, 256>>>(x);
    dim3 tb(32, 8);
    k_wt<<<dim3(9, 36, NCK), tb>>>(W0, W1, W2, W3);

    dim3 gg(NCOL / BN, (NN + BM - 1) / BM);
    k_gemm<<<gg, 128, SMEM_GEMM>>>(B0v, B1v, B2v, B3v);

    cudaStreamWaitEvent(0, evB, 0);

    // Clenshaw: conv c (K=4+c) starts at t = 3-c; all finals land at t = 5
    for (int t = 0; t < 6; t++) {
        CleArgs A;
        int nact = 0;
        for (int c = 3; c >= 0; c--) {
            const int ts = 3 - c;
            if (t < ts) continue;
            const int K = 4 + c;
            const int s = t - ts;
            const int k = K - 2 - s;
            const int a = nact++;
            if (s == 0) A.srcH[a] = XWcolH(c);
            else        A.srcH[a] = PbufH(c, (s - 1) & 1);
            if (s == 0)      A.prv[a] = nullptr;
            else if (s == 1) A.prv[a] = XWcol(c, K - 1);
            else             A.prv[a] = Pbuf(c, s & 1);
            if (s == K - 2) {
                A.dst[a] = out + c * FOUT; A.dstr4[a] = (4 * FOUT) / 4;
                A.dstH[a] = nullptr; A.coef[a] = 1.f;
            } else {
                A.dst[a] = Pbuf(c, s & 1); A.dstr4[a] = FOUT / 4;
                A.dstH[a] = PbufH(c, s & 1); A.coef[a] = 2.f;
            }
            A.xw[a] = XWcol(c, k);
        }
        switch (nact) {
            case 1: k_cle<1><<<NN, 288>>>(A); break;
            case 2: k_cle<2><<<NN, 288>>>(A); break;
            case 3: k_cle<3><<<NN, 288>>>(A); break;
            default: k_cle<4><<<NN, 288>>>(A); break;
        }
    }
}

// round 17
// speedup vs baseline: 1.2309x; 1.0309x over previous
#include <cuda_runtime.h>
#include <cuda_fp16.h>
#include <cstdint>

#define NN   10000
#define EE   160000
#define FIN  1152
#define FOUT 288
#define NCK  22                 /* total (conv,k) pairs: 4+5+6+7 */
#define NCOL (NCK*FOUT)         /* 6336 */

// ---------------- device scratch ----------------------------------------------
__device__ __half g_Xh[(size_t)NN * FIN];              // fp16 x (GEMM A)
__device__ __half g_Wh[(size_t)NCOL * FIN];            // fp16 W K-major [ncol][f]
__device__ __half g_XWh[(size_t)NCK * NN * FOUT];      // X@W products, fp16 z-major
__device__ float  g_P[(size_t)8 * NN * FOUT];          // Clenshaw ping-pong (fp32)
__device__ __half g_Ph[(size_t)8 * NN * FOUT];         // fp16 shadow (gather source)

__device__ int   g_deg[NN];
__device__ float g_dinv[NN];
__device__ int   g_cnt[NN];
__device__ int   g_colptr[NN + 1];
__device__ int   g_cursor[NN];
__device__ int   g_src[EE];
__device__ float g_w[EE];

// ---------------- helpers -------------------------------------------------------
__device__ __forceinline__ uint32_t smem_u32(const void* p) {
    return (uint32_t)__cvta_generic_to_shared(p);
}
__device__ __forceinline__ void cp16(uint32_t s, const void* g) {
    asm volatile("cp.async.cg.shared.global [%0], [%1], 16;"
                 :: "r"(s), "l"(__cvta_generic_to_global(g)) : "memory");
}
__device__ __forceinline__ void mma_f16(float* d, const uint32_t* a, const uint32_t* b) {
    asm volatile(
        "mma.sync.aligned.m16n8k16.row.col.f32.f16.f16.f32 "
        "{%0,%1,%2,%3}, {%4,%5,%6,%7}, {%8,%9}, {%0,%1,%2,%3};"
        : "+f"(d[0]), "+f"(d[1]), "+f"(d[2]), "+f"(d[3])
        : "r"(a[0]), "r"(a[1]), "r"(a[2]), "r"(a[3]), "r"(b[0]), "r"(b[1]));
}
__device__ __forceinline__ void ldsm4(uint32_t* r, uint32_t addr) {
    asm volatile("ldmatrix.sync.aligned.m8n8.x4.shared.b16 {%0,%1,%2,%3}, [%4];"
                 : "=r"(r[0]), "=r"(r[1]), "=r"(r[2]), "=r"(r[3]) : "r"(addr));
}
__device__ __forceinline__ void ldsm2(uint32_t* r, uint32_t addr) {
    asm volatile("ldmatrix.sync.aligned.m8n8.x2.shared.b16 {%0,%1}, [%2];"
                 : "=r"(r[0]), "=r"(r[1]) : "r"(addr));
}
__device__ __forceinline__ float4 h4_to_f4(uint2 u) {
    float2 f01 = __half22float2(*(__half2*)&u.x);
    float2 f23 = __half22float2(*(__half2*)&u.y);
    return make_float4(f01.x, f01.y, f23.x, f23.y);
}

// ---------------- setup kernels ------------------------------------------------
__global__ void k_zero() {
    int i = blockIdx.x * blockDim.x + threadIdx.x;
    if (i < NN) { g_deg[i] = 0; g_cnt[i] = 0; g_cursor[i] = 0; }
}
__global__ void k_hist(const int* __restrict__ ei) {
    int e = blockIdx.x * blockDim.x + threadIdx.x;
    if (e < EE) {
        atomicAdd(&g_deg[ei[e]], 1);
        atomicAdd(&g_cnt[ei[EE + e]], 1);
    }
}
__global__ void k_scan() {
    __shared__ int wsum[32];
    const int tid  = threadIdx.x;
    const int lane = tid & 31;
    const int warp = tid >> 5;

    int v[10];
    int s = 0;
#pragma unroll
    for (int i = 0; i < 10; i++) {
        int idx = tid * 10 + i;
        if (idx < NN) {
            v[i] = g_cnt[idx];
            int dg = g_deg[idx];
            g_dinv[idx] = (dg > 0) ? rsqrtf((float)dg) : 0.0f;
        } else v[i] = 0;
        s += v[i];
    }
    int inc = s;
#pragma unroll
    for (int off = 1; off < 32; off <<= 1) {
        int n = __shfl_up_sync(0xFFFFFFFF, inc, off);
        if (lane >= off) inc += n;
    }
    if (lane == 31) wsum[warp] = inc;
    __syncthreads();
    if (warp == 0) {
        int w = wsum[lane];
#pragma unroll
        for (int off = 1; off < 32; off <<= 1) {
            int n = __shfl_up_sync(0xFFFFFFFF, w, off);
            if (lane >= off) w += n;
        }
        wsum[lane] = w;
    }
    __syncthreads();
    int base = (warp > 0 ? wsum[warp - 1] : 0) + inc - s;
#pragma unroll
    for (int i = 0; i < 10; i++) {
        int idx = tid * 10 + i;
        if (idx < NN) g_colptr[idx] = base;
        base += v[i];
    }
    if (tid == 1023) g_colptr[NN] = wsum[31];
}
__global__ void k_scatter(const int* __restrict__ ei) {
    int e = blockIdx.x * blockDim.x + threadIdx.x;
    if (e < EE) {
        int r = ei[e];
        int c = ei[EE + e];
        int p = g_colptr[c] + atomicAdd(&g_cursor[c], 1);
        g_src[p] = r;
        g_w[p]   = -(g_dinv[r] * g_dinv[c]);
    }
}
__global__ void k_xh(const float* __restrict__ x) {
    const int total = NN * (FIN / 4);
    for (int idx = blockIdx.x * blockDim.x + threadIdx.x; idx < total;
         idx += gridDim.x * blockDim.x) {
        float4 v = ((const float4*)x)[idx];
        __half2* dst = (__half2*)(g_Xh + (size_t)idx * 4);
        dst[0] = __floats2half2_rn(v.x, v.y);
        dst[1] = __floats2half2_rn(v.z, v.w);
    }
}
// W[c][kk][f][o] fp32 -> g_Wh[((offs[c]+kk)*288+o)][f] fp16
__global__ void k_wt(const float* __restrict__ W0, const float* __restrict__ W1,
                     const float* __restrict__ W2, const float* __restrict__ W3) {
    __shared__ float tile[32][33];
    const int z = blockIdx.z;
    int c, kk;
    if (z < 4)      { c = 0; kk = z; }
    else if (z < 9) { c = 1; kk = z - 4; }
    else if (z < 15){ c = 2; kk = z - 9; }
    else            { c = 3; kk = z - 15; }
    const float* W = (c == 0) ? W0 : (c == 1) ? W1 : (c == 2) ? W2 : W3;
    const float* Wk = W + (size_t)kk * FIN * FOUT;
    const int ncol0 = z * FOUT + blockIdx.x * 32;
    const int f0 = blockIdx.y * 32;
    const int tx = threadIdx.x, ty = threadIdx.y;
#pragma unroll
    for (int r = 0; r < 4; r++) {
        int a = ty + 8 * r;
        tile[a][tx] = Wk[(size_t)(f0 + a) * FOUT + blockIdx.x * 32 + tx];
    }
    __syncthreads();
#pragma unroll
    for (int r = 0; r < 4; r++) {
        int a = ty + 8 * r;
        g_Wh[(size_t)(ncol0 + a) * FIN + f0 + tx] = __float2half_rn(tile[tx][a]);
    }
}

// ---------------- fp16 mma.sync GEMM (fp16-only z-major XW output) ---------------
#define BM 128
#define BN 144
#define BK 32
#define ASTRH 40
#define BSTRH 40
#define STAGES 5
#define A_STH (BM*ASTRH)
#define B_STH (BN*BSTRH)
#define STG_H (A_STH + B_STH)
#define SMEM_GEMM (STAGES*STG_H*2)           /* 108800 B */
#define NTILES (FIN/BK)                      /* 36 */

__global__ void __launch_bounds__(128, 2) k_gemm(
    const float* __restrict__ B0, const float* __restrict__ B1,
    const float* __restrict__ B2, const float* __restrict__ B3)
{
    extern __shared__ __align__(16) __half smp[];
    const uint32_t sbase = smem_u32(smp);

    const int m0  = blockIdx.y * BM;
    const int n0  = blockIdx.x * BN;
    const int z   = blockIdx.x >> 1;
    const float* Bv = (z == 0) ? B0 : (z == 4) ? B1 : (z == 9) ? B2
                    : (z == 15) ? B3 : nullptr;
    const int bcol0 = (blockIdx.x & 1) * BN;
    __half* xwh = g_XWh + (size_t)z * NN * FOUT;

    const int t   = threadIdx.x;
    const int lane = t & 31;
    const int wid  = t >> 5;
    const int warpM = wid >> 1;
    const int warpN = wid & 1;
    const int lq = lane >> 2;
    const int lr = lane & 3;

    const int a_lm = (warpM * 64 + (lane & 7) + (lane & 8)) * ASTRH + ((lane & 16) >> 1);
    const int b_lm = (warpN * 72 + (lane & 7) + ((lane & 16) >> 1)) * BSTRH + (lane & 8);
    const int bs_lm = (warpN * 72 + 64 + (lane & 7)) * BSTRH + (lane & 8);

    const int ar0 = t >> 2, ach = (t & 3) * 8;
    const __half* a_src[4];
    uint32_t a_dst[4];
#pragma unroll
    for (int i = 0; i < 4; i++) {
        int row = ar0 + 32 * i;
        int gm = m0 + row; gm = (gm < NN) ? gm : (NN - 1);
        a_src[i] = g_Xh + (size_t)gm * FIN + ach;
        a_dst[i] = sbase + (row * ASTRH + ach) * 2;
    }
    int brow[5], bch[5];
#pragma unroll
    for (int i = 0; i < 5; i++) {
        int j = t + 128 * i;
        brow[i] = j >> 2;
        bch[i]  = (j & 3) * 8;
    }
    const bool b5 = (t < 64);
    uint32_t b_dst[5];
    const __half* b_src[5];
#pragma unroll
    for (int i = 0; i < 5; i++) {
        b_dst[i] = sbase + (A_STH + brow[i] * BSTRH + bch[i]) * 2;
        b_src[i] = g_Wh + (size_t)(n0 + brow[i]) * FIN + bch[i];
    }

    float d[4][9][4];
#pragma unroll
    for (int i = 0; i < 4; i++)
#pragma unroll
        for (int j = 0; j < 9; j++)
#pragma unroll
            for (int q = 0; q < 4; q++) d[i][j][q] = 0.f;

#pragma unroll
    for (int s = 0; s < STAGES - 1; s++) {
        const int k0 = s * BK;
        const uint32_t so = s * (STG_H * 2);
#pragma unroll
        for (int i = 0; i < 4; i++) cp16(a_dst[i] + so, a_src[i] + k0);
#pragma unroll
        for (int i = 0; i < 4; i++) cp16(b_dst[i] + so, b_src[i] + k0);
        if (b5) cp16(b_dst[4] + so, b_src[4] + k0);
        asm volatile("cp.async.commit_group;" ::: "memory");
    }

    uint32_t af[2][4][4], bf[2][9][2];

    asm volatile("cp.async.wait_group %0;" :: "n"(STAGES - 3) : "memory");
    __syncthreads();
    {
        const uint32_t sA = sbase;
        const uint32_t sB = sbase + A_STH * 2;
#pragma unroll
        for (int mt = 0; mt < 4; mt++)
            ldsm4(af[0][mt], sA + (a_lm + mt * 16 * ASTRH) * 2);
#pragma unroll
        for (int np = 0; np < 4; np++) {
            uint32_t r4[4];
            ldsm4(r4, sB + (b_lm + np * 16 * BSTRH) * 2);
            bf[0][2 * np][0] = r4[0]; bf[0][2 * np][1] = r4[1];
            bf[0][2 * np + 1][0] = r4[2]; bf[0][2 * np + 1][1] = r4[3];
        }
        ldsm2(bf[0][8], sB + bs_lm * 2);
    }

    for (int it = 0; it < NTILES; ++it) {
        if (it > 0) {
            asm volatile("cp.async.wait_group %0;" :: "n"(STAGES - 3) : "memory");
            __syncthreads();
        }
        {
            const int ld = it + STAGES - 1;
            if (ld < NTILES) {
                const int s = ld % STAGES;
                const int k0 = ld * BK;
                const uint32_t so = s * (STG_H * 2);
#pragma unroll
                for (int i = 0; i < 4; i++) cp16(a_dst[i] + so, a_src[i] + k0);
#pragma unroll
                for (int i = 0; i < 4; i++) cp16(b_dst[i] + so, b_src[i] + k0);
                if (b5) cp16(b_dst[4] + so, b_src[4] + k0);
            }
            asm volatile("cp.async.commit_group;" ::: "memory");
        }

        const int cs = it % STAGES;
        const uint32_t sA = sbase + cs * (STG_H * 2);
        const uint32_t sB = sA + A_STH * 2;

#pragma unroll
        for (int mt = 0; mt < 4; mt++)
            ldsm4(af[1][mt], sA + (a_lm + mt * 16 * ASTRH + 16) * 2);
#pragma unroll
        for (int np = 0; np < 4; np++) {
            uint32_t r4[4];
            ldsm4(r4, sB + (b_lm + np * 16 * BSTRH + 16) * 2);
            bf[1][2 * np][0] = r4[0]; bf[1][2 * np][1] = r4[1];
            bf[1][2 * np + 1][0] = r4[2]; bf[1][2 * np + 1][1] = r4[3];
        }
        ldsm2(bf[1][8], sB + (bs_lm + 16) * 2);
#pragma unroll
        for (int mt = 0; mt < 4; mt++)
#pragma unroll
            for (int nt = 0; nt < 9; nt++)
                mma_f16(d[mt][nt], af[0][mt], bf[0][nt]);

        if (it + 1 < NTILES) {
            const int ns = (it + 1) % STAGES;
            const uint32_t nA = sbase + ns * (STG_H * 2);
            const uint32_t nB = nA + A_STH * 2;
#pragma unroll
            for (int mt = 0; mt < 4; mt++)
                ldsm4(af[0][mt], nA + (a_lm + mt * 16 * ASTRH) * 2);
#pragma unroll
            for (int np = 0; np < 4; np++) {
                uint32_t r4[4];
                ldsm4(r4, nB + (b_lm + np * 16 * BSTRH) * 2);
                bf[0][2 * np][0] = r4[0]; bf[0][2 * np][1] = r4[1];
                bf[0][2 * np + 1][0] = r4[2]; bf[0][2 * np + 1][1] = r4[3];
            }
            ldsm2(bf[0][8], nB + bs_lm * 2);
        }
#pragma unroll
        for (int mt = 0; mt < 4; mt++)
#pragma unroll
            for (int nt = 0; nt < 9; nt++)
                mma_f16(d[mt][nt], af[1][mt], bf[1][nt]);
    }

    // epilogue -> fp16 z-major XW (+bias on k==0 product columns)
#pragma unroll
    for (int mt = 0; mt < 4; mt++) {
        const int row0 = m0 + warpM * 64 + mt * 16 + lq;
        const int row1 = row0 + 8;
#pragma unroll
        for (int nt = 0; nt < 9; nt++) {
            const int col = bcol0 + warpN * 72 + nt * 8 + lr * 2;
            float bx = 0.f, by = 0.f;
            if (Bv) { bx = __ldg(&Bv[col]); by = __ldg(&Bv[col + 1]); }
            if (row0 < NN)
                *(__half2*)&xwh[(size_t)row0 * FOUT + col] =
                    __floats2half2_rn(d[mt][nt][0] + bx, d[mt][nt][1] + by);
            if (row1 < NN)
                *(__half2*)&xwh[(size_t)row1 * FOUT + col] =
                    __floats2half2_rn(d[mt][nt][2] + bx, d[mt][nt][3] + by);
        }
    }
}

// ---------------- Clenshaw step kernel (fp16 gathers + fp16 xw, fp32 state) ------
struct CleArgs {
    const __half* srcH[4];                     // fp16 gather source, node stride FOUT
    const __half* xwH[4];                      // fp16 xw term, node stride FOUT
    const float*  prvF[4];                     // fp32 P prv (s>=2); null otherwise
    const __half* prvH[4];                     // fp16 XW prv (s==1); null otherwise
    float*        dst[4]; int dstr4[4];        // fp32 out (finals stride 4*FOUT)
    __half*       dstH[4];                     // fp16 shadow; null for finals
    float coef[4];
};

// 288 threads: thread t -> (chain a = t/72, col4 = t%72); uint2 (4 halves)/edge.
template <int NACT>
__global__ void __launch_bounds__(288) k_cle(CleArgs A) {
    const int node = blockIdx.x;
    const int tid  = threadIdx.x;
    const int a    = tid / 72;
    const int c4   = tid % 72;
    const bool act = (a < NACT);

    const int beg  = g_colptr[node];
    const int end  = g_colptr[node + 1];

    __shared__ int   ss[64];
    __shared__ float sw[64];

    const __half* srcp = act ? (A.srcH[a] + c4 * 4) : nullptr;

    float4 acc = make_float4(0.f, 0.f, 0.f, 0.f);

    for (int b0 = beg; b0 < end; b0 += 64) {
        int cnt = min(64, end - b0);
        __syncthreads();
        if (tid < cnt) { ss[tid] = g_src[b0 + tid]; sw[tid] = g_w[b0 + tid]; }
        __syncthreads();
        if (act) {
            for (int j = 0; j < cnt; j++) {
                const float w = sw[j];
                float4 f = h4_to_f4(*(const uint2*)(srcp + (size_t)ss[j] * FOUT));
                acc.x += w * f.x; acc.y += w * f.y;
                acc.z += w * f.z; acc.w += w * f.w;
            }
        }
    }

    if (act) {
        const float  cf = A.coef[a];
        const float4 x4 = h4_to_f4(*(const uint2*)(A.xwH[a] + (size_t)node * FOUT + c4 * 4));
        float4 v;
        v.x = x4.x + cf * acc.x; v.y = x4.y + cf * acc.y;
        v.z = x4.z + cf * acc.z; v.w = x4.w + cf * acc.w;
        if (A.prvF[a]) {
            const float4 p = ((const float4*)A.prvF[a])[(size_t)node * (FOUT / 4) + c4];
            v.x -= p.x; v.y -= p.y; v.z -= p.z; v.w -= p.w;
        } else if (A.prvH[a]) {
            const float4 p = h4_to_f4(*(const uint2*)(A.prvH[a] + (size_t)node * FOUT + c4 * 4));
            v.x -= p.x; v.y -= p.y; v.z -= p.z; v.w -= p.w;
        }
        ((float4*)A.dst[a])[(size_t)node * A.dstr4[a] + c4] = v;
        if (A.dstH[a]) {
            uint2 h;
            *(__half2*)&h.x = __floats2half2_rn(v.x, v.y);
            *(__half2*)&h.y = __floats2half2_rn(v.z, v.w);
            *(uint2*)(A.dstH[a] + (size_t)node * FOUT + c4 * 4) = h;
        }
    }
}

// ---------------- launch --------------------------------------------------------
extern "C" void kernel_launch(void* const* d_in, const int* in_sizes, int n_in,
                              void* d_out, int out_size) {
    const float* x   = (const float*)d_in[0];
    const int*   ei  = (const int*)d_in[1];
    const float* W0  = (const float*)d_in[2];
    const float* B0v = (const float*)d_in[3];
    const float* W1  = (const float*)d_in[4];
    const float* B1v = (const float*)d_in[5];
    const float* W2  = (const float*)d_in[6];
    const float* B2v = (const float*)d_in[7];
    const float* W3  = (const float*)d_in[8];
    const float* B3v = (const float*)d_in[9];
    float* out = (float*)d_out;

    static float*  pP   = nullptr;
    static __half* pXWh = nullptr;
    static __half* pPh  = nullptr;
    static cudaStream_t s1 = nullptr;
    static cudaEvent_t evA = nullptr, evB = nullptr;
    if (!pP) {
        void* p;
        cudaGetSymbolAddress(&p, g_P);   pP   = (float*)p;
        cudaGetSymbolAddress(&p, g_XWh); pXWh = (__half*)p;
        cudaGetSymbolAddress(&p, g_Ph);  pPh  = (__half*)p;
        cudaFuncSetAttribute(k_gemm, cudaFuncAttributeMaxDynamicSharedMemorySize, SMEM_GEMM);
        cudaStreamCreateWithFlags(&s1, cudaStreamNonBlocking);
        cudaEventCreateWithFlags(&evA, cudaEventDisableTiming);
        cudaEventCreateWithFlags(&evB, cudaEventDisableTiming);
    }
    static const int offs[4] = {0, 4, 9, 15};
    auto XWslab = [&](int c, int kk) { return pXWh + (size_t)(offs[c] + kk) * NN * FOUT; };
    auto Pbuf   = [&](int c, int par) { return pP + (size_t)(c * 2 + par) * NN * FOUT; };
    auto PbufH  = [&](int c, int par) { return pPh + (size_t)(c * 2 + par) * NN * FOUT; };

    // fork: edge preprocessing on s1 (tiny), concurrent with conversion + GEMM
    cudaEventRecord(evA, 0);
    cudaStreamWaitEvent(s1, evA, 0);
    k_zero<<<(NN + 255) / 256, 256, 0, s1>>>();
    k_hist<<<(EE + 255) / 256, 256, 0, s1>>>(ei);
    k_scan<<<1, 1024, 0, s1>>>();
    k_scatter<<<(EE + 255) / 256, 256, 0, s1>>>(ei);
    cudaEventRecord(evB, s1);

    k_xh<<<2048, 256>>>(x);
    dim3 tb(32, 8);
    k_wt<<<dim3(9, 36, NCK), tb>>>(W0, W1, W2, W3);

    dim3 gg(NCOL / BN, (NN + BM - 1) / BM);
    k_gemm<<<gg, 128, SMEM_GEMM>>>(B0v, B1v, B2v, B3v);

    cudaStreamWaitEvent(0, evB, 0);

    // Clenshaw: conv c (K=4+c) starts at t = 3-c; all finals land at t = 5
    for (int t = 0; t < 6; t++) {
        CleArgs A;
        int nact = 0;
        for (int c = 3; c >= 0; c--) {
            const int ts = 3 - c;
            if (t < ts) continue;
            const int K = 4 + c;
            const int s = t - ts;
            const int k = K - 2 - s;
            const int a = nact++;
            if (s == 0) A.srcH[a] = XWslab(c, K - 1);
            else        A.srcH[a] = PbufH(c, (s - 1) & 1);
            A.prvF[a] = nullptr; A.prvH[a] = nullptr;
            if (s == 1)      A.prvH[a] = XWslab(c, K - 1);
            else if (s >= 2) A.prvF[a] = Pbuf(c, s & 1);
            if (s == K - 2) {
                A.dst[a] = out + c * FOUT; A.dstr4[a] = (4 * FOUT) / 4;
                A.dstH[a] = nullptr; A.coef[a] = 1.f;
            } else {
                A.dst[a] = Pbuf(c, s & 1); A.dstr4[a] = FOUT / 4;
                A.dstH[a] = PbufH(c, s & 1); A.coef[a] = 2.f;
            }
            A.xwH[a] = XWslab(c, k);
        }
        switch (nact) {
            case 1: k_cle<1><<<NN, 288>>>(A); break;
            case 2: k_cle<2><<<NN, 288>>>(A); break;
            case 3: k_cle<3><<<NN, 288>>>(A); break;
            default: k_cle<4><<<NN, 288>>>(A); break;
        }
    }
}